// round 4
// baseline (speedup 1.0000x reference)
#include <cuda_runtime.h>
#include <cstdint>

#define TT 500
#define BB 64
#define FF 256
#define HH 512
#define OO 128

#define CL 8       // CTAs per cluster (one batch group)
#define HC 64      // h rows per scan CTA
#define WS 65      // padded smem stride for wT

#define NSCAN 64   // scan CTAs (8 clusters x 8)
#define NWORK 80   // GEMM worker CTAs
#define NTILE_M 250            // (TT*BB)/128
#define NTILES (NTILE_M * 4)   // x 4 n-tiles

#define NCHUNK 10
#define CHLEN 50   // TT / NCHUNK

// ---- scratch (device globals: no allocation allowed) ----
__device__ float    g_xproj[(size_t)TT * BB * HH];      // 65.5 MB
__device__ unsigned g_spk[(size_t)TT * BB * (HH / 32)]; // 2 MB spike bitmasks
__device__ float    g_lin[(size_t)TT * BB * OO];        // 16 MB
__device__ float    g_woutT[HH * OO];                   // 256 KB
__device__ int      g_tileready[NTILE_M];               // xproj m-tile ready counters
__device__ float    g_ytail[BB * NCHUNK * OO];          // filter chunk tails

// ============================================================
// K0: transpose w_out [O,H] -> g_woutT [H,O]
// ============================================================
__global__ void k_wtrans(const float* __restrict__ w_out) {
    int idx = blockIdx.x * blockDim.x + threadIdx.x;
    if (idx < HH * OO) {
        int h = idx >> 7, o = idx & 127;
        g_woutT[idx] = w_out[o * HH + h];
    }
}

// ============================================================
// K1 (mega): scan CTAs (bid<64) + xproj worker CTAs (bid>=64), one launch.
// ============================================================
__global__ void __launch_bounds__(512, 1) __cluster_dims__(CL, 1, 1)
k_mega(const float* __restrict__ x, const float* __restrict__ w_in,
       const float* __restrict__ w_rec, float* __restrict__ d_out) {
    extern __shared__ float smem[];
    int tid = threadIdx.x;
    int bid = blockIdx.x;

    if (bid >= NSCAN) {
        // -------- xproj worker: tiles of x_proj[m,h] = sum_f x[m,f]*w_in[h,f]
        float* As = smem;              // [16][132]
        float* Bs = smem + 16 * 132;   // [16][132]
        int w = bid - NSCAN;
        int tx = tid & 15, ty = tid >> 4;   // 16 x 32 thread grid
        for (int tile = w; tile < NTILES; tile += NWORK) {
            int mt = tile >> 2, nt = tile & 3;
            int mBase = mt * 128, nBase = nt * 128;
            float acc[4][8] = {};
            for (int k0 = 0; k0 < FF; k0 += 16) {
                int row = tid >> 2, c4 = tid & 3;
                float4 va = *(const float4*)(x + (size_t)(mBase + row) * FF + k0 + c4 * 4);
                As[(c4 * 4 + 0) * 132 + row] = va.x;
                As[(c4 * 4 + 1) * 132 + row] = va.y;
                As[(c4 * 4 + 2) * 132 + row] = va.z;
                As[(c4 * 4 + 3) * 132 + row] = va.w;
                float4 vb = *(const float4*)(w_in + (size_t)(nBase + row) * FF + k0 + c4 * 4);
                Bs[(c4 * 4 + 0) * 132 + row] = vb.x;
                Bs[(c4 * 4 + 1) * 132 + row] = vb.y;
                Bs[(c4 * 4 + 2) * 132 + row] = vb.z;
                Bs[(c4 * 4 + 3) * 132 + row] = vb.w;
                __syncthreads();
#pragma unroll
                for (int k = 0; k < 16; k++) {
                    float a[4], b[8];
                    *(float4*)(a)     = *(const float4*)&As[k * 132 + ty * 4];
                    *(float4*)(b)     = *(const float4*)&Bs[k * 132 + tx * 8];
                    *(float4*)(b + 4) = *(const float4*)&Bs[k * 132 + tx * 8 + 4];
#pragma unroll
                    for (int i2 = 0; i2 < 4; i2++)
#pragma unroll
                        for (int j = 0; j < 8; j++)
                            acc[i2][j] += a[i2] * b[j];
                }
                __syncthreads();
            }
#pragma unroll
            for (int i2 = 0; i2 < 4; i2++) {
                float* op = g_xproj + (size_t)(mBase + ty * 4 + i2) * HH + nBase + tx * 8;
                *(float4*)(op)     = make_float4(acc[i2][0], acc[i2][1], acc[i2][2], acc[i2][3]);
                *(float4*)(op + 4) = make_float4(acc[i2][4], acc[i2][5], acc[i2][6], acc[i2][7]);
            }
            __threadfence();
            __syncthreads();
            if (tid == 0) atomicAdd(&g_tileready[mt], 1);
        }
        return;
    }

    // -------- LIF-AdEx scan CTA --------
    float* wT = smem;                                  // [512][WS] transposed W_rec slice
    unsigned* mbox = (unsigned*)(smem + HH * WS);      // [2][8][2] ballot words

    int lane = tid & 31, warp = tid >> 5;              // warp 0..15
    int bl = warp >> 1;                                // batch_local 0..7
    int half = warp & 1;
    unsigned r;
    asm("mov.u32 %0, %%cluster_ctarank;" : "=r"(r));   // 0..7
    int g = bid >> 3;                                  // batch group 0..7
    int b = g * 8 + bl;
    int hl = half * 32 + lane;                         // 0..63
    int h = (int)r * HC + hl;

    // load transposed W_rec slice: wT[j*WS + hh] = w_rec[r*64+hh][j]
    for (int idx = tid; idx < HH * HC; idx += 512) {
        int j = idx & (HH - 1);
        int hh = idx >> 9;
        wT[(size_t)j * WS + hh] = w_rec[(size_t)((int)r * HC + hh) * HH + j];
    }

    uint32_t mbox_u32;
    {
        uint64_t tmp;
        asm("cvta.to.shared.u64 %0, %1;" : "=l"(tmp) : "l"(mbox));
        mbox_u32 = (uint32_t)tmp;
    }

    // wait for xproj tile 0 (timesteps 0,1)
    if (tid == 0) {
        while (((volatile int*)g_tileready)[0] < 4) { }
        __threadfence();
    }
    __syncthreads();

    float v = 0.f, cur = 0.f, aa = 0.f;
    bool z = false;
    float xp_next = g_xproj[(size_t)b * HH + h];  // t=0

    for (int t = 0; t < TT; t++) {
        float irec = 0.f;
        if (t > 0) {
            int buf = (t - 1) & 1;
            unsigned val = 0;
            if (lane < 16) {
                int srcr = lane >> 1;
                uint32_t la = mbox_u32 + (unsigned)(((buf * 8 + bl) * 2 + (lane & 1)) * 4);
                uint32_t pa;
                asm("mapa.shared::cluster.u32 %0, %1, %2;" : "=r"(pa) : "r"(la), "r"(srcr));
                asm("ld.shared::cluster.b32 %0, [%1];" : "=r"(val) : "r"(pa));
            }
#pragma unroll
            for (int w16 = 0; w16 < 16; w16++) {
                unsigned m = __shfl_sync(0xffffffffu, val, w16);
                const float* wp = wT + (size_t)(w16 * 32) * WS + hl;
                while (m) {
                    int j = __ffs(m) - 1;
                    m &= m - 1;
                    irec += wp[(size_t)j * WS];
                }
            }
        }

        float xp = xp_next;
        if (t + 1 < TT) {
            if (((t + 1) & 1) == 0) {                  // new xproj m-tile
                int mt = (t + 1) >> 1;
                if (tid == 0) {
                    while (((volatile int*)g_tileready)[mt] < 4) { }
                    __threadfence();
                }
                __syncthreads();
            }
            xp_next = g_xproj[(size_t)((t + 1) * BB + b) * HH + h];
        }

        // LIF-AdEx step (all from OLD state; ordering matches reference)
        float ex = expf((v - 1.0f) * 2.0f);                       // exp((v-V_TH)/DELTA_T)
        float dv = 0.1f * ((((0.0f - v) + 0.5f * ex) + cur) - aa);
        float v_dec = v + dv;
        float i_dec = cur - 0.2f * cur;
        float a_dec = aa + 0.002f * (4.0f * v - aa);
        z = (v_dec - 1.0f) > 0.0f;
        v = z ? 0.0f : v_dec;
        cur = (i_dec + xp) + irec;
        aa = a_dec + (z ? 0.02f : 0.0f);

        unsigned bits = __ballot_sync(0xffffffffu, z);
        if (lane == 0) {
            mbox[((t & 1) * 8 + bl) * 2 + half] = bits;
            g_spk[(size_t)(t * BB + b) * 16 + (int)r * 2 + half] = bits;
        }

        asm volatile("barrier.cluster.arrive.aligned;" ::: "memory");
        asm volatile("barrier.cluster.wait.aligned;" ::: "memory");
    }

    // final states (z, v, i, a) appended after out[T,B,O]
    size_t base = (size_t)TT * BB * OO;
    size_t off = (size_t)b * HH + h;
    d_out[base + off] = z ? 1.0f : 0.0f;
    d_out[base + BB * HH + off] = v;
    d_out[base + 2 * BB * HH + off] = cur;
    d_out[base + 3 * BB * HH + off] = aa;
}

// ============================================================
// K3: lin[t,b,o] = b_out[o] + sum over spiking h of w_outT[h][o]
//     (block 0 also resets g_tileready for the next graph replay)
// ============================================================
__global__ void __launch_bounds__(128) k_lin(const float* __restrict__ b_out) {
    __shared__ unsigned zw[16];
    int tb = blockIdx.x;
    int tid = threadIdx.x;
    if (tb == 0) {
        for (int i = tid; i < NTILE_M; i += 128) g_tileready[i] = 0;
    }
    if (tid < 16) zw[tid] = g_spk[(size_t)tb * 16 + tid];
    __syncthreads();
    float acc = 0.f;
#pragma unroll
    for (int w16 = 0; w16 < 16; w16++) {
        unsigned m = zw[w16];
        const float* wp = g_woutT + (size_t)w16 * 32 * OO + tid;
        while (m) {
            int j = __ffs(m) - 1;
            m &= m - 1;
            acc += wp[j * OO];
        }
    }
    g_lin[(size_t)tb * OO + tid] = acc + b_out[tid];
}

// ============================================================
// K4a: filter phase A — local exp-filter scan per 50-step chunk (zero init)
// ============================================================
__global__ void __launch_bounds__(128) k_filter_a(float* __restrict__ out) {
    int b = blockIdx.x;       // 64
    int c = blockIdx.y;       // 10
    int o = threadIdx.x;      // 128
    const float C = (float)(0.001 * 223.1435511314);
    float y = 0.f;
    int t0 = c * CHLEN;
    for (int t = t0; t < t0 + CHLEN; t++) {
        float l = g_lin[((size_t)t * BB + b) * OO + o];
        y = y + C * (l - y);
        out[((size_t)t * BB + b) * OO + o] = y;
    }
    g_ytail[(b * NCHUNK + c) * OO + o] = y;
}

// ============================================================
// K4b: filter phase B — add carry correction d^(k+1) * carry_c
// ============================================================
__global__ void __launch_bounds__(128) k_filter_b(float* __restrict__ out) {
    int b = blockIdx.x;           // 64
    int c = blockIdx.y + 1;       // 1..9
    int o = threadIdx.x;          // 128
    const float C = (float)(0.001 * 223.1435511314);
    const float D = 1.0f - C;
    // D^CHLEN
    float d50 = 1.0f;
    for (int i = 0; i < CHLEN; i++) d50 *= D;
    // carry entering chunk c
    float carry = 0.f;
    for (int j = 1; j <= c; j++)
        carry = g_ytail[(b * NCHUNK + (j - 1)) * OO + o] + d50 * carry;
    int t0 = c * CHLEN;
    float p = D;
    for (int t = t0; t < t0 + CHLEN; t++) {
        out[((size_t)t * BB + b) * OO + o] += p * carry;
        p *= D;
    }
}

// ============================================================
extern "C" void kernel_launch(void* const* d_in, const int* in_sizes, int n_in,
                              void* d_out, int out_size) {
    const float* x     = (const float*)d_in[0];  // [500,64,256]
    const float* w_in  = (const float*)d_in[1];  // [512,256]
    const float* w_rec = (const float*)d_in[2];  // [512,512]
    const float* w_out = (const float*)d_in[3];  // [128,512]
    const float* b_out = (const float*)d_in[4];  // [128]
    float* out = (float*)d_out;

    const int scan_smem = HH * WS * 4 + 2 * 8 * 2 * 4;  // 133248 B
    static bool attr_set = false;
    if (!attr_set) {
        cudaFuncSetAttribute(k_mega, cudaFuncAttributeMaxDynamicSharedMemorySize, scan_smem);
        attr_set = true;
    }

    k_wtrans<<<(HH * OO + 255) / 256, 256>>>(w_out);
    k_mega<<<NSCAN + NWORK, 512, scan_smem>>>(x, w_in, w_rec, out);
    k_lin<<<TT * BB, 128>>>(b_out);
    k_filter_a<<<dim3(BB, NCHUNK), 128>>>(out);
    k_filter_b<<<dim3(BB, NCHUNK - 1), 128>>>(out);
}

// round 5
// speedup vs baseline: 1.1049x; 1.1049x over previous
#include <cuda_runtime.h>
#include <cstdint>

#define TT 500
#define BB 64
#define FF 256
#define HH 512
#define OO 128

#define NCHUNK 10
#define CHLEN 50   // TT / NCHUNK

// ---- scratch (device globals: no allocation allowed) ----
__device__ float    g_xproj[(size_t)TT * BB * HH];      // 65.5 MB
__device__ unsigned g_spk[(size_t)TT * BB * (HH / 32)]; // 2 MB spike bitmasks
__device__ float    g_lin[(size_t)TT * BB * OO];        // 16 MB
__device__ float    g_woutT[HH * OO];                   // 256 KB
__device__ float    g_wrecT[HH * HH];                   // 1 MB, w_rec transposed
__device__ float    g_ytail[BB * NCHUNK * OO];          // filter chunk tails

// ============================================================
// K0a: transpose w_out [O,H] -> g_woutT [H,O]
// ============================================================
__global__ void k_wtrans(const float* __restrict__ w_out) {
    int idx = blockIdx.x * blockDim.x + threadIdx.x;
    if (idx < HH * OO) {
        int h = idx >> 7, o = idx & 127;
        g_woutT[idx] = w_out[o * HH + h];
    }
}

// ============================================================
// K0b: transpose w_rec [H,H] -> g_wrecT  (g_wrecT[j][i] = w_rec[i][j])
// ============================================================
__global__ void k_wrect(const float* __restrict__ w_rec) {
    __shared__ float tile[32][33];
    int bx = blockIdx.x * 32, by = blockIdx.y * 32;
    int tx = threadIdx.x, ty = threadIdx.y;   // 32 x 8
#pragma unroll
    for (int i = 0; i < 32; i += 8)
        tile[ty + i][tx] = w_rec[(size_t)(by + ty + i) * HH + bx + tx];
    __syncthreads();
#pragma unroll
    for (int i = 0; i < 32; i += 8)
        g_wrecT[(size_t)(bx + ty + i) * HH + by + tx] = tile[tx][ty + i];
}

// ============================================================
// K1: x_proj[m,h] = sum_f x[m,f] * w_in[h,f]  (M=32000,K=256,N=512)
// 128x128 tile, BK=16, 256 threads, 8x8 per thread
// ============================================================
__global__ void __launch_bounds__(256) k_xproj(const float* __restrict__ A,
                                               const float* __restrict__ B) {
    __shared__ float As[16][132];
    __shared__ float Bs[16][132];
    int tid = threadIdx.x;
    int tx = tid & 15, ty = tid >> 4;     // 16 x 16 thread grid
    int mBase = blockIdx.x * 128;
    int nBase = blockIdx.y * 128;
    float acc[8][8] = {};
    for (int k0 = 0; k0 < FF; k0 += 16) {
#pragma unroll
        for (int i = 0; i < 2; i++) {
            int li = tid + i * 256;       // 0..511
            int row = li >> 2;            // 0..127
            int c4 = li & 3;
            float4 va = *(const float4*)(A + (size_t)(mBase + row) * FF + k0 + c4 * 4);
            As[c4 * 4 + 0][row] = va.x;
            As[c4 * 4 + 1][row] = va.y;
            As[c4 * 4 + 2][row] = va.z;
            As[c4 * 4 + 3][row] = va.w;
            float4 vb = *(const float4*)(B + (size_t)(nBase + row) * FF + k0 + c4 * 4);
            Bs[c4 * 4 + 0][row] = vb.x;
            Bs[c4 * 4 + 1][row] = vb.y;
            Bs[c4 * 4 + 2][row] = vb.z;
            Bs[c4 * 4 + 3][row] = vb.w;
        }
        __syncthreads();
#pragma unroll
        for (int k = 0; k < 16; k++) {
            float a[8], b[8];
            *(float4*)(a)     = *(const float4*)&As[k][ty * 8];
            *(float4*)(a + 4) = *(const float4*)&As[k][ty * 8 + 4];
            *(float4*)(b)     = *(const float4*)&Bs[k][tx * 8];
            *(float4*)(b + 4) = *(const float4*)&Bs[k][tx * 8 + 4];
#pragma unroll
            for (int i2 = 0; i2 < 8; i2++)
#pragma unroll
                for (int j = 0; j < 8; j++)
                    acc[i2][j] += a[i2] * b[j];
        }
        __syncthreads();
    }
#pragma unroll
    for (int i2 = 0; i2 < 8; i2++) {
        float* op = g_xproj + (size_t)(mBase + ty * 8 + i2) * HH + nBase + tx * 8;
        *(float4*)(op)     = make_float4(acc[i2][0], acc[i2][1], acc[i2][2], acc[i2][3]);
        *(float4*)(op + 4) = make_float4(acc[i2][4], acc[i2][5], acc[i2][6], acc[i2][7]);
    }
}

// ============================================================
// K2: LIF-AdEx scan — ONE CTA PER BATCH, one thread per h.
// Batches are independent: no inter-CTA sync at all.
// W_recT stays L2/L1-resident; spikes exchanged via smem ballot words.
// ============================================================
__global__ void __launch_bounds__(512, 1)
k_scan(float* __restrict__ d_out) {
    __shared__ unsigned zsm[2][16];
    int tid = threadIdx.x;            // = h
    int b = blockIdx.x;               // batch
    int lane = tid & 31, warp = tid >> 5;

    float v = 0.f, cur = 0.f, aa = 0.f;
    bool z = false;
    float xp_next = g_xproj[(size_t)b * HH + tid];   // t=0 prefetch

    for (int t = 0; t < TT; t++) {
        float irec = 0.f;
        if (t > 0) {
            const unsigned* zr = zsm[(t - 1) & 1];
#pragma unroll
            for (int w16 = 0; w16 < 16; w16++) {
                unsigned m = zr[w16];                 // LDS broadcast
                const float* wp = g_wrecT + (size_t)(w16 * 32) * HH + tid;
                while (m) {
                    int j = __ffs(m) - 1;
                    m &= m - 1;
                    irec += wp[(size_t)j * HH];       // coalesced, L1-reused row
                }
            }
        }

        float xp = xp_next;
        if (t + 1 < TT) xp_next = g_xproj[(size_t)((t + 1) * BB + b) * HH + tid];

        // LIF-AdEx step (all from OLD state; ordering matches reference)
        float ex = expf((v - 1.0f) * 2.0f);                       // exp((v-V_TH)/DELTA_T)
        float dv = 0.1f * ((((0.0f - v) + 0.5f * ex) + cur) - aa);
        float v_dec = v + dv;
        float i_dec = cur - 0.2f * cur;
        float a_dec = aa + 0.002f * (4.0f * v - aa);
        z = (v_dec - 1.0f) > 0.0f;
        v = z ? 0.0f : v_dec;
        cur = (i_dec + xp) + irec;
        aa = a_dec + (z ? 0.02f : 0.0f);

        unsigned bits = __ballot_sync(0xffffffffu, z);
        if (lane == 0) {
            zsm[t & 1][warp] = bits;
            g_spk[(size_t)(t * BB + b) * 16 + warp] = bits;
        }
        __syncthreads();   // orders this step's reads/writes vs next step
    }

    // final states (z, v, i, a) appended after out[T,B,O]
    size_t base = (size_t)TT * BB * OO;
    size_t off = (size_t)b * HH + tid;
    d_out[base + off] = z ? 1.0f : 0.0f;
    d_out[base + BB * HH + off] = v;
    d_out[base + 2 * BB * HH + off] = cur;
    d_out[base + 3 * BB * HH + off] = aa;
}

// ============================================================
// K3: lin[t,b,o] = b_out[o] + sum over spiking h of w_outT[h][o]
// ============================================================
__global__ void __launch_bounds__(128) k_lin(const float* __restrict__ b_out) {
    __shared__ unsigned zw[16];
    int tb = blockIdx.x;
    int tid = threadIdx.x;
    if (tid < 16) zw[tid] = g_spk[(size_t)tb * 16 + tid];
    __syncthreads();
    float acc = 0.f;
#pragma unroll
    for (int w16 = 0; w16 < 16; w16++) {
        unsigned m = zw[w16];
        const float* wp = g_woutT + (size_t)w16 * 32 * OO + tid;
        while (m) {
            int j = __ffs(m) - 1;
            m &= m - 1;
            acc += wp[j * OO];
        }
    }
    g_lin[(size_t)tb * OO + tid] = acc + b_out[tid];
}

// ============================================================
// K4a: filter phase A — local exp-filter scan per 50-step chunk (zero init)
// ============================================================
__global__ void __launch_bounds__(128) k_filter_a(float* __restrict__ out) {
    int b = blockIdx.x;       // 64
    int c = blockIdx.y;       // 10
    int o = threadIdx.x;      // 128
    const float C = (float)(0.001 * 223.1435511314);
    float y = 0.f;
    int t0 = c * CHLEN;
    for (int t = t0; t < t0 + CHLEN; t++) {
        float l = g_lin[((size_t)t * BB + b) * OO + o];
        y = y + C * (l - y);
        out[((size_t)t * BB + b) * OO + o] = y;
    }
    g_ytail[(b * NCHUNK + c) * OO + o] = y;
}

// ============================================================
// K4b: filter phase B — add carry correction d^(k+1) * carry_c
// ============================================================
__global__ void __launch_bounds__(128) k_filter_b(float* __restrict__ out) {
    int b = blockIdx.x;           // 64
    int c = blockIdx.y + 1;       // 1..9
    int o = threadIdx.x;          // 128
    const float C = (float)(0.001 * 223.1435511314);
    const float D = 1.0f - C;
    float d50 = 1.0f;
    for (int i = 0; i < CHLEN; i++) d50 *= D;
    float carry = 0.f;
    for (int j = 1; j <= c; j++)
        carry = g_ytail[(b * NCHUNK + (j - 1)) * OO + o] + d50 * carry;
    int t0 = c * CHLEN;
    float p = D;
    for (int t = t0; t < t0 + CHLEN; t++) {
        out[((size_t)t * BB + b) * OO + o] += p * carry;
        p *= D;
    }
}

// ============================================================
extern "C" void kernel_launch(void* const* d_in, const int* in_sizes, int n_in,
                              void* d_out, int out_size) {
    const float* x     = (const float*)d_in[0];  // [500,64,256]
    const float* w_in  = (const float*)d_in[1];  // [512,256]
    const float* w_rec = (const float*)d_in[2];  // [512,512]
    const float* w_out = (const float*)d_in[3];  // [128,512]
    const float* b_out = (const float*)d_in[4];  // [128]
    float* out = (float*)d_out;

    k_wtrans<<<(HH * OO + 255) / 256, 256>>>(w_out);
    k_wrect<<<dim3(16, 16), dim3(32, 8)>>>(w_rec);
    k_xproj<<<dim3((TT * BB) / 128, HH / 128), 256>>>(x, w_in);
    k_scan<<<BB, 512>>>(out);
    k_lin<<<TT * BB, 128>>>(b_out);
    k_filter_a<<<dim3(BB, NCHUNK), 128>>>(out);
    k_filter_b<<<dim3(BB, NCHUNK - 1), 128>>>(out);
}

// round 6
// speedup vs baseline: 1.6673x; 1.5091x over previous
#include <cuda_runtime.h>
#include <cstdint>

#define TT 500
#define BB 64
#define FF 256
#define HH 512
#define OO 128

#define NCHUNK 10
#define CHLEN 50   // TT / NCHUNK

// ---- scratch (device globals: no allocation allowed) ----
__device__ float    g_xproj[(size_t)TT * BB * HH];      // 65.5 MB
__device__ unsigned g_spk[(size_t)TT * BB * (HH / 32)]; // 2 MB spike bitmasks
__device__ float    g_lin[(size_t)TT * BB * OO];        // 16 MB
__device__ float    g_woutT[HH * OO];                   // 256 KB
__device__ float    g_wrecT[HH * HH];                   // 1 MB, w_rec transposed
__device__ float    g_ytail[BB * NCHUNK * OO];          // filter chunk tails

// ============================================================
// K0a: transpose w_out [O,H] -> g_woutT [H,O]
// ============================================================
__global__ void k_wtrans(const float* __restrict__ w_out) {
    int idx = blockIdx.x * blockDim.x + threadIdx.x;
    if (idx < HH * OO) {
        int h = idx >> 7, o = idx & 127;
        g_woutT[idx] = w_out[o * HH + h];
    }
}

// ============================================================
// K0b: transpose w_rec [H,H] -> g_wrecT  (g_wrecT[j][i] = w_rec[i][j])
// ============================================================
__global__ void k_wrect(const float* __restrict__ w_rec) {
    __shared__ float tile[32][33];
    int bx = blockIdx.x * 32, by = blockIdx.y * 32;
    int tx = threadIdx.x, ty = threadIdx.y;   // 32 x 8
#pragma unroll
    for (int i = 0; i < 32; i += 8)
        tile[ty + i][tx] = w_rec[(size_t)(by + ty + i) * HH + bx + tx];
    __syncthreads();
#pragma unroll
    for (int i = 0; i < 32; i += 8)
        g_wrecT[(size_t)(bx + ty + i) * HH + by + tx] = tile[tx][ty + i];
}

// ============================================================
// K1: x_proj[m,h] = sum_f x[m,f] * w_in[h,f]  (M=32000,K=256,N=512)
// 128x128 tile, BK=16, 256 threads, 8x8 per thread  (unchanged from R5)
// ============================================================
__global__ void __launch_bounds__(256) k_xproj(const float* __restrict__ A,
                                               const float* __restrict__ B) {
    __shared__ float As[16][132];
    __shared__ float Bs[16][132];
    int tid = threadIdx.x;
    int tx = tid & 15, ty = tid >> 4;
    int mBase = blockIdx.x * 128;
    int nBase = blockIdx.y * 128;
    float acc[8][8] = {};
    for (int k0 = 0; k0 < FF; k0 += 16) {
#pragma unroll
        for (int i = 0; i < 2; i++) {
            int li = tid + i * 256;
            int row = li >> 2;
            int c4 = li & 3;
            float4 va = *(const float4*)(A + (size_t)(mBase + row) * FF + k0 + c4 * 4);
            As[c4 * 4 + 0][row] = va.x;
            As[c4 * 4 + 1][row] = va.y;
            As[c4 * 4 + 2][row] = va.z;
            As[c4 * 4 + 3][row] = va.w;
            float4 vb = *(const float4*)(B + (size_t)(nBase + row) * FF + k0 + c4 * 4);
            Bs[c4 * 4 + 0][row] = vb.x;
            Bs[c4 * 4 + 1][row] = vb.y;
            Bs[c4 * 4 + 2][row] = vb.z;
            Bs[c4 * 4 + 3][row] = vb.w;
        }
        __syncthreads();
#pragma unroll
        for (int k = 0; k < 16; k++) {
            float a[8], b[8];
            *(float4*)(a)     = *(const float4*)&As[k][ty * 8];
            *(float4*)(a + 4) = *(const float4*)&As[k][ty * 8 + 4];
            *(float4*)(b)     = *(const float4*)&Bs[k][tx * 8];
            *(float4*)(b + 4) = *(const float4*)&Bs[k][tx * 8 + 4];
#pragma unroll
            for (int i2 = 0; i2 < 8; i2++)
#pragma unroll
                for (int j = 0; j < 8; j++)
                    acc[i2][j] += a[i2] * b[j];
        }
        __syncthreads();
    }
#pragma unroll
    for (int i2 = 0; i2 < 8; i2++) {
        float* op = g_xproj + (size_t)(mBase + ty * 8 + i2) * HH + nBase + tx * 8;
        *(float4*)(op)     = make_float4(acc[i2][0], acc[i2][1], acc[i2][2], acc[i2][3]);
        *(float4*)(op + 4) = make_float4(acc[i2][4], acc[i2][5], acc[i2][6], acc[i2][7]);
    }
}

// ============================================================
// K2: LIF-AdEx scan — one CTA per batch, 256 threads.
// Thread t owns h=t and h=t+256 (so ballots give standard spike words).
// Per step: build dense offset list (benign-race, all warps identical),
// then counted gather loop from L2-resident w_recT. One barrier/step.
// Gather order: ascending j (bit-identical to previous rounds).
// ============================================================
__global__ void __launch_bounds__(256, 1)
k_scan(float* __restrict__ d_out) {
    __shared__ unsigned zsm[2][16];
    __shared__ int offs[HH];

    int tid = threadIdx.x;            // = h_a; h_b = tid + 256
    int b = blockIdx.x;               // batch
    int lane = tid & 31, warp = tid >> 5;   // warp 0..7

    float va = 0.f, ia = 0.f, aa = 0.f;
    float vb = 0.f, ib = 0.f, ab = 0.f;
    bool za = false, zb = false;

    float xa_next = g_xproj[(size_t)b * HH + tid];
    float xb_next = g_xproj[(size_t)b * HH + tid + 256];

    for (int t = 0; t < TT; t++) {
        float ra = 0.f, rb = 0.f;
        if (t > 0) {
            int buf = (t - 1) & 1;
            // ---- build offset list (all warps do identical work; benign race)
            unsigned mword = (lane < 16) ? zsm[buf][lane] : 0u;
            int cnt = __popc(mword);
            int pfx = cnt;
#pragma unroll
            for (int d = 1; d < 32; d <<= 1) {
                int y = __shfl_up_sync(0xffffffffu, pfx, d);
                if (lane >= d) pfx += y;
            }
            int n = __shfl_sync(0xffffffffu, pfx, 31);
            int base = pfx - cnt;
            while (mword) {
                int bit = __ffs(mword) - 1;
                mword &= mword - 1;
                offs[base++] = ((lane << 5) + bit) << 11;   // j * 512 floats * 4B
            }
            __syncwarp();
            // ---- dense gather (ascending j)
#pragma unroll 4
            for (int s = 0; s < n; s++) {
                const float* wp = (const float*)((const char*)g_wrecT + offs[s]);
                ra += wp[tid];
                rb += wp[tid + 256];
            }
        }

        float xa = xa_next, xb = xb_next;
        if (t + 1 < TT) {
            xa_next = g_xproj[(size_t)((t + 1) * BB + b) * HH + tid];
            xb_next = g_xproj[(size_t)((t + 1) * BB + b) * HH + tid + 256];
        }

        // LIF-AdEx step for h_a
        {
            float ex = expf((va - 1.0f) * 2.0f);
            float dv = 0.1f * ((((0.0f - va) + 0.5f * ex) + ia) - aa);
            float v_dec = va + dv;
            float i_dec = ia - 0.2f * ia;
            float a_dec = aa + 0.002f * (4.0f * va - aa);
            za = (v_dec - 1.0f) > 0.0f;
            va = za ? 0.0f : v_dec;
            ia = (i_dec + xa) + ra;
            aa = a_dec + (za ? 0.02f : 0.0f);
        }
        // LIF-AdEx step for h_b
        {
            float ex = expf((vb - 1.0f) * 2.0f);
            float dv = 0.1f * ((((0.0f - vb) + 0.5f * ex) + ib) - ab);
            float v_dec = vb + dv;
            float i_dec = ib - 0.2f * ib;
            float a_dec = ab + 0.002f * (4.0f * vb - ab);
            zb = (v_dec - 1.0f) > 0.0f;
            vb = zb ? 0.0f : v_dec;
            ib = (i_dec + xb) + rb;
            ab = a_dec + (zb ? 0.02f : 0.0f);
        }

        unsigned ba = __ballot_sync(0xffffffffu, za);   // word 'warp'   (h = warp*32+lane)
        unsigned bb2 = __ballot_sync(0xffffffffu, zb);  // word 'warp+8' (h = 256 + ...)
        if (lane == 0) {
            zsm[t & 1][warp] = ba;
            zsm[t & 1][warp + 8] = bb2;
            unsigned* gs = g_spk + (size_t)(t * BB + b) * 16;
            gs[warp] = ba;
            gs[warp + 8] = bb2;
        }
        __syncthreads();
    }

    // final states (z, v, i, a) appended after out[T,B,O]
    size_t base = (size_t)TT * BB * OO;
    size_t oa = (size_t)b * HH + tid;
    size_t ob = oa + 256;
    d_out[base + oa] = za ? 1.0f : 0.0f;
    d_out[base + ob] = zb ? 1.0f : 0.0f;
    d_out[base + BB * HH + oa] = va;
    d_out[base + BB * HH + ob] = vb;
    d_out[base + 2 * BB * HH + oa] = ia;
    d_out[base + 2 * BB * HH + ob] = ib;
    d_out[base + 3 * BB * HH + oa] = aa;
    d_out[base + 3 * BB * HH + ob] = ab;
}

// ============================================================
// K3: lin[t,b,o] = b_out[o] + sum over spiking h of w_outT[h][o]
// ============================================================
__global__ void __launch_bounds__(128) k_lin(const float* __restrict__ b_out) {
    __shared__ unsigned zw[16];
    int tb = blockIdx.x;
    int tid = threadIdx.x;
    if (tid < 16) zw[tid] = g_spk[(size_t)tb * 16 + tid];
    __syncthreads();
    float acc = 0.f;
#pragma unroll
    for (int w16 = 0; w16 < 16; w16++) {
        unsigned m = zw[w16];
        const float* wp = g_woutT + (size_t)w16 * 32 * OO + tid;
        while (m) {
            int j = __ffs(m) - 1;
            m &= m - 1;
            acc += wp[j * OO];
        }
    }
    g_lin[(size_t)tb * OO + tid] = acc + b_out[tid];
}

// ============================================================
// K4a: filter phase A — local exp-filter scan per 50-step chunk (zero init)
// ============================================================
__global__ void __launch_bounds__(128) k_filter_a(float* __restrict__ out) {
    int b = blockIdx.x;
    int c = blockIdx.y;
    int o = threadIdx.x;
    const float C = (float)(0.001 * 223.1435511314);
    float y = 0.f;
    int t0 = c * CHLEN;
    for (int t = t0; t < t0 + CHLEN; t++) {
        float l = g_lin[((size_t)t * BB + b) * OO + o];
        y = y + C * (l - y);
        out[((size_t)t * BB + b) * OO + o] = y;
    }
    g_ytail[(b * NCHUNK + c) * OO + o] = y;
}

// ============================================================
// K4b: filter phase B — add carry correction d^(k+1) * carry_c
// ============================================================
__global__ void __launch_bounds__(128) k_filter_b(float* __restrict__ out) {
    int b = blockIdx.x;
    int c = blockIdx.y + 1;
    int o = threadIdx.x;
    const float C = (float)(0.001 * 223.1435511314);
    const float D = 1.0f - C;
    float d50 = 1.0f;
    for (int i = 0; i < CHLEN; i++) d50 *= D;
    float carry = 0.f;
    for (int j = 1; j <= c; j++)
        carry = g_ytail[(b * NCHUNK + (j - 1)) * OO + o] + d50 * carry;
    int t0 = c * CHLEN;
    float p = D;
    for (int t = t0; t < t0 + CHLEN; t++) {
        out[((size_t)t * BB + b) * OO + o] += p * carry;
        p *= D;
    }
}

// ============================================================
extern "C" void kernel_launch(void* const* d_in, const int* in_sizes, int n_in,
                              void* d_out, int out_size) {
    const float* x     = (const float*)d_in[0];  // [500,64,256]
    const float* w_in  = (const float*)d_in[1];  // [512,256]
    const float* w_rec = (const float*)d_in[2];  // [512,512]
    const float* w_out = (const float*)d_in[3];  // [128,512]
    const float* b_out = (const float*)d_in[4];  // [128]
    float* out = (float*)d_out;

    k_wtrans<<<(HH * OO + 255) / 256, 256>>>(w_out);
    k_wrect<<<dim3(16, 16), dim3(32, 8)>>>(w_rec);
    k_xproj<<<dim3((TT * BB) / 128, HH / 128), 256>>>(x, w_in);
    k_scan<<<BB, 256>>>(out);
    k_lin<<<TT * BB, 128>>>(b_out);
    k_filter_a<<<dim3(BB, NCHUNK), 128>>>(out);
    k_filter_b<<<dim3(BB, NCHUNK - 1), 128>>>(out);
}

// round 7
// speedup vs baseline: 1.8706x; 1.1219x over previous
#include <cuda_runtime.h>
#include <cstdint>

#define TT 500
#define BB 64
#define FF 256
#define HH 512
#define OO 128

#define NCHUNK 10
#define CHLEN 50   // TT / NCHUNK

// ---- scratch (device globals: no allocation allowed) ----
__device__ float    g_xproj[(size_t)TT * BB * HH];      // 65.5 MB
__device__ unsigned g_spk[(size_t)TT * BB * (HH / 32)]; // 2 MB spike bitmasks
__device__ float    g_lin[(size_t)TT * BB * OO];        // 16 MB
__device__ float    g_woutT[HH * OO];                   // 256 KB
__device__ float    g_wrecT[HH * HH];                   // 1 MB, w_rec transposed
__device__ float    g_ytail[BB * NCHUNK * OO];          // filter chunk tails

// ============================================================
// K0a: transpose w_out [O,H] -> g_woutT [H,O]
// ============================================================
__global__ void k_wtrans(const float* __restrict__ w_out) {
    int idx = blockIdx.x * blockDim.x + threadIdx.x;
    if (idx < HH * OO) {
        int h = idx >> 7, o = idx & 127;
        g_woutT[idx] = w_out[o * HH + h];
    }
}

// ============================================================
// K0b: transpose w_rec [H,H] -> g_wrecT  (g_wrecT[j][i] = w_rec[i][j])
// ============================================================
__global__ void k_wrect(const float* __restrict__ w_rec) {
    __shared__ float tile[32][33];
    int bx = blockIdx.x * 32, by = blockIdx.y * 32;
    int tx = threadIdx.x, ty = threadIdx.y;   // 32 x 8
#pragma unroll
    for (int i = 0; i < 32; i += 8)
        tile[ty + i][tx] = w_rec[(size_t)(by + ty + i) * HH + bx + tx];
    __syncthreads();
#pragma unroll
    for (int i = 0; i < 32; i += 8)
        g_wrecT[(size_t)(bx + ty + i) * HH + by + tx] = tile[tx][ty + i];
}

// ============================================================
// K1: x_proj[m,h] = sum_f x[m,f] * w_in[h,f]  (M=32000,K=256,N=512)
// 128x128 tile, BK=16, 256 threads, 8x8 per thread
// ============================================================
__global__ void __launch_bounds__(256) k_xproj(const float* __restrict__ A,
                                               const float* __restrict__ B) {
    __shared__ float As[16][132];
    __shared__ float Bs[16][132];
    int tid = threadIdx.x;
    int tx = tid & 15, ty = tid >> 4;
    int mBase = blockIdx.x * 128;
    int nBase = blockIdx.y * 128;
    float acc[8][8] = {};
    for (int k0 = 0; k0 < FF; k0 += 16) {
#pragma unroll
        for (int i = 0; i < 2; i++) {
            int li = tid + i * 256;
            int row = li >> 2;
            int c4 = li & 3;
            float4 va = *(const float4*)(A + (size_t)(mBase + row) * FF + k0 + c4 * 4);
            As[c4 * 4 + 0][row] = va.x;
            As[c4 * 4 + 1][row] = va.y;
            As[c4 * 4 + 2][row] = va.z;
            As[c4 * 4 + 3][row] = va.w;
            float4 vb = *(const float4*)(B + (size_t)(nBase + row) * FF + k0 + c4 * 4);
            Bs[c4 * 4 + 0][row] = vb.x;
            Bs[c4 * 4 + 1][row] = vb.y;
            Bs[c4 * 4 + 2][row] = vb.z;
            Bs[c4 * 4 + 3][row] = vb.w;
        }
        __syncthreads();
#pragma unroll
        for (int k = 0; k < 16; k++) {
            float a[8], b[8];
            *(float4*)(a)     = *(const float4*)&As[k][ty * 8];
            *(float4*)(a + 4) = *(const float4*)&As[k][ty * 8 + 4];
            *(float4*)(b)     = *(const float4*)&Bs[k][tx * 8];
            *(float4*)(b + 4) = *(const float4*)&Bs[k][tx * 8 + 4];
#pragma unroll
            for (int i2 = 0; i2 < 8; i2++)
#pragma unroll
                for (int j = 0; j < 8; j++)
                    acc[i2][j] += a[i2] * b[j];
        }
        __syncthreads();
    }
#pragma unroll
    for (int i2 = 0; i2 < 8; i2++) {
        float* op = g_xproj + (size_t)(mBase + ty * 8 + i2) * HH + nBase + tx * 8;
        *(float4*)(op)     = make_float4(acc[i2][0], acc[i2][1], acc[i2][2], acc[i2][3]);
        *(float4*)(op + 4) = make_float4(acc[i2][4], acc[i2][5], acc[i2][6], acc[i2][7]);
    }
}

// ============================================================
// K2: LIF-AdEx scan — one CTA per batch, 256 threads, h = {tid, tid+256}.
// Gather restructured into batches of 8: 16 independent LDG in flight,
// adds applied in ascending-j order (bit-identical trajectory).
// ============================================================
__global__ void __launch_bounds__(256, 1)
k_scan(float* __restrict__ d_out) {
    __shared__ unsigned zsm[2][16];
    __shared__ int offs[HH];

    int tid = threadIdx.x;            // = h_a; h_b = tid + 256
    int b = blockIdx.x;               // batch
    int lane = tid & 31, warp = tid >> 5;   // warp 0..7

    const char* base_a = (const char*)g_wrecT + (size_t)tid * 4;
    const char* base_b = base_a + 256 * 4;

    float va = 0.f, ia = 0.f, aa = 0.f;
    float vb = 0.f, ib = 0.f, ab = 0.f;
    bool za = false, zb = false;

    float xa_next = g_xproj[(size_t)b * HH + tid];
    float xb_next = g_xproj[(size_t)b * HH + tid + 256];

    for (int t = 0; t < TT; t++) {
        float ra = 0.f, rb = 0.f;
        if (t > 0) {
            int buf = (t - 1) & 1;
            // ---- build offset list (all warps duplicate; benign race, same values)
            unsigned mword = (lane < 16) ? zsm[buf][lane] : 0u;
            int cnt = __popc(mword);
            int pfx = cnt;
#pragma unroll
            for (int d = 1; d < 32; d <<= 1) {
                int y = __shfl_up_sync(0xffffffffu, pfx, d);
                if (lane >= d) pfx += y;
            }
            int n = __shfl_sync(0xffffffffu, pfx, 31);
            int base = pfx - cnt;
            while (mword) {
                int bit = __ffs(mword) - 1;
                mword &= mword - 1;
                offs[base++] = ((lane << 5) + bit) << 11;   // j * 512 floats * 4B
            }
            __syncwarp();

            // ---- dense gather, 8 rows per batch: 16 independent loads in flight
            int s = 0;
            for (; s + 8 <= n; s += 8) {
                int4 o0 = *(const int4*)&offs[s];
                int4 o1 = *(const int4*)&offs[s + 4];
                float a0 = *(const float*)(base_a + o0.x);
                float a1 = *(const float*)(base_a + o0.y);
                float a2 = *(const float*)(base_a + o0.z);
                float a3 = *(const float*)(base_a + o0.w);
                float a4 = *(const float*)(base_a + o1.x);
                float a5 = *(const float*)(base_a + o1.y);
                float a6 = *(const float*)(base_a + o1.z);
                float a7 = *(const float*)(base_a + o1.w);
                float b0 = *(const float*)(base_b + o0.x);
                float b1 = *(const float*)(base_b + o0.y);
                float b2 = *(const float*)(base_b + o0.z);
                float b3 = *(const float*)(base_b + o0.w);
                float b4 = *(const float*)(base_b + o1.x);
                float b5 = *(const float*)(base_b + o1.y);
                float b6 = *(const float*)(base_b + o1.z);
                float b7 = *(const float*)(base_b + o1.w);
                // ascending-j order preserved
                ra += a0; ra += a1; ra += a2; ra += a3;
                ra += a4; ra += a5; ra += a6; ra += a7;
                rb += b0; rb += b1; rb += b2; rb += b3;
                rb += b4; rb += b5; rb += b6; rb += b7;
            }
            for (; s < n; s++) {
                int o = offs[s];
                ra += *(const float*)(base_a + o);
                rb += *(const float*)(base_b + o);
            }
        }

        float xa = xa_next, xb = xb_next;
        if (t + 1 < TT) {
            xa_next = g_xproj[(size_t)((t + 1) * BB + b) * HH + tid];
            xb_next = g_xproj[(size_t)((t + 1) * BB + b) * HH + tid + 256];
        }

        // LIF-AdEx step for h_a
        {
            float ex = expf((va - 1.0f) * 2.0f);
            float dv = 0.1f * ((((0.0f - va) + 0.5f * ex) + ia) - aa);
            float v_dec = va + dv;
            float i_dec = ia - 0.2f * ia;
            float a_dec = aa + 0.002f * (4.0f * va - aa);
            za = (v_dec - 1.0f) > 0.0f;
            va = za ? 0.0f : v_dec;
            ia = (i_dec + xa) + ra;
            aa = a_dec + (za ? 0.02f : 0.0f);
        }
        // LIF-AdEx step for h_b
        {
            float ex = expf((vb - 1.0f) * 2.0f);
            float dv = 0.1f * ((((0.0f - vb) + 0.5f * ex) + ib) - ab);
            float v_dec = vb + dv;
            float i_dec = ib - 0.2f * ib;
            float a_dec = ab + 0.002f * (4.0f * vb - ab);
            zb = (v_dec - 1.0f) > 0.0f;
            vb = zb ? 0.0f : v_dec;
            ib = (i_dec + xb) + rb;
            ab = a_dec + (zb ? 0.02f : 0.0f);
        }

        unsigned ba = __ballot_sync(0xffffffffu, za);   // word 'warp'
        unsigned bb2 = __ballot_sync(0xffffffffu, zb);  // word 'warp+8'
        if (lane == 0) {
            zsm[t & 1][warp] = ba;
            zsm[t & 1][warp + 8] = bb2;
            unsigned* gs = g_spk + (size_t)(t * BB + b) * 16;
            gs[warp] = ba;
            gs[warp + 8] = bb2;
        }
        __syncthreads();
    }

    // final states (z, v, i, a) appended after out[T,B,O]
    size_t base = (size_t)TT * BB * OO;
    size_t oa = (size_t)b * HH + tid;
    size_t ob = oa + 256;
    d_out[base + oa] = za ? 1.0f : 0.0f;
    d_out[base + ob] = zb ? 1.0f : 0.0f;
    d_out[base + BB * HH + oa] = va;
    d_out[base + BB * HH + ob] = vb;
    d_out[base + 2 * BB * HH + oa] = ia;
    d_out[base + 2 * BB * HH + ob] = ib;
    d_out[base + 3 * BB * HH + oa] = aa;
    d_out[base + 3 * BB * HH + ob] = ab;
}

// ============================================================
// K3: lin[t,b,o] = b_out[o] + sum over spiking h of w_outT[h][o]
// ============================================================
__global__ void __launch_bounds__(128) k_lin(const float* __restrict__ b_out) {
    __shared__ unsigned zw[16];
    int tb = blockIdx.x;
    int tid = threadIdx.x;
    if (tid < 16) zw[tid] = g_spk[(size_t)tb * 16 + tid];
    __syncthreads();
    float acc = 0.f;
#pragma unroll
    for (int w16 = 0; w16 < 16; w16++) {
        unsigned m = zw[w16];
        const float* wp = g_woutT + (size_t)w16 * 32 * OO + tid;
        while (m) {
            int j = __ffs(m) - 1;
            m &= m - 1;
            acc += wp[j * OO];
        }
    }
    g_lin[(size_t)tb * OO + tid] = acc + b_out[tid];
}

// ============================================================
// K4a: filter phase A — local exp-filter scan per 50-step chunk (zero init)
// ============================================================
__global__ void __launch_bounds__(128) k_filter_a(float* __restrict__ out) {
    int b = blockIdx.x;
    int c = blockIdx.y;
    int o = threadIdx.x;
    const float C = (float)(0.001 * 223.1435511314);
    float y = 0.f;
    int t0 = c * CHLEN;
    for (int t = t0; t < t0 + CHLEN; t++) {
        float l = g_lin[((size_t)t * BB + b) * OO + o];
        y = y + C * (l - y);
        out[((size_t)t * BB + b) * OO + o] = y;
    }
    g_ytail[(b * NCHUNK + c) * OO + o] = y;
}

// ============================================================
// K4b: filter phase B — add carry correction d^(k+1) * carry_c
// ============================================================
__global__ void __launch_bounds__(128) k_filter_b(float* __restrict__ out) {
    int b = blockIdx.x;
    int c = blockIdx.y + 1;
    int o = threadIdx.x;
    const float C = (float)(0.001 * 223.1435511314);
    const float D = 1.0f - C;
    float d50 = 1.0f;
    for (int i = 0; i < CHLEN; i++) d50 *= D;
    float carry = 0.f;
    for (int j = 1; j <= c; j++)
        carry = g_ytail[(b * NCHUNK + (j - 1)) * OO + o] + d50 * carry;
    int t0 = c * CHLEN;
    float p = D;
    for (int t = t0; t < t0 + CHLEN; t++) {
        out[((size_t)t * BB + b) * OO + o] += p * carry;
        p *= D;
    }
}

// ============================================================
extern "C" void kernel_launch(void* const* d_in, const int* in_sizes, int n_in,
                              void* d_out, int out_size) {
    const float* x     = (const float*)d_in[0];  // [500,64,256]
    const float* w_in  = (const float*)d_in[1];  // [512,256]
    const float* w_rec = (const float*)d_in[2];  // [512,512]
    const float* w_out = (const float*)d_in[3];  // [128,512]
    const float* b_out = (const float*)d_in[4];  // [128]
    float* out = (float*)d_out;

    k_wtrans<<<(HH * OO + 255) / 256, 256>>>(w_out);
    k_wrect<<<dim3(16, 16), dim3(32, 8)>>>(w_rec);
    k_xproj<<<dim3((TT * BB) / 128, HH / 128), 256>>>(x, w_in);
    k_scan<<<BB, 256>>>(out);
    k_lin<<<TT * BB, 128>>>(b_out);
    k_filter_a<<<dim3(BB, NCHUNK), 128>>>(out);
    k_filter_b<<<dim3(BB, NCHUNK - 1), 128>>>(out);
}

// round 8
// speedup vs baseline: 1.8720x; 1.0007x over previous
#include <cuda_runtime.h>
#include <cstdint>

#define TT 500
#define BB 64
#define FF 256
#define HH 512
#define OO 128

#define NCHUNK 10
#define CHLEN 50   // TT / NCHUNK

// ---- scratch (device globals: no allocation allowed) ----
__device__ float    g_xproj[(size_t)TT * BB * HH];      // 65.5 MB
__device__ unsigned g_spk[(size_t)TT * BB * (HH / 32)]; // 2 MB spike bitmasks
__device__ float    g_lin[(size_t)TT * BB * OO];        // 16 MB
__device__ float    g_woutT[HH * OO];                   // 256 KB
__device__ float    g_wrecT[HH * HH];                   // 1 MB, w_rec transposed
__device__ float    g_ytail[BB * NCHUNK * OO];          // filter chunk tails

// ============================================================
// K0a: transpose w_out [O,H] -> g_woutT [H,O]
// ============================================================
__global__ void k_wtrans(const float* __restrict__ w_out) {
    int idx = blockIdx.x * blockDim.x + threadIdx.x;
    if (idx < HH * OO) {
        int h = idx >> 7, o = idx & 127;
        g_woutT[idx] = w_out[o * HH + h];
    }
}

// ============================================================
// K0b: transpose w_rec [H,H] -> g_wrecT  (g_wrecT[j][i] = w_rec[i][j])
// ============================================================
__global__ void k_wrect(const float* __restrict__ w_rec) {
    __shared__ float tile[32][33];
    int bx = blockIdx.x * 32, by = blockIdx.y * 32;
    int tx = threadIdx.x, ty = threadIdx.y;   // 32 x 8
#pragma unroll
    for (int i = 0; i < 32; i += 8)
        tile[ty + i][tx] = w_rec[(size_t)(by + ty + i) * HH + bx + tx];
    __syncthreads();
#pragma unroll
    for (int i = 0; i < 32; i += 8)
        g_wrecT[(size_t)(bx + ty + i) * HH + by + tx] = tile[tx][ty + i];
}

// ============================================================
// K1: x_proj[m,h] = sum_f x[m,f] * w_in[h,f]  (M=32000,K=256,N=512)
// 128x128 tile, BK=16, 256 threads, 8x8 per thread
// ============================================================
__global__ void __launch_bounds__(256) k_xproj(const float* __restrict__ A,
                                               const float* __restrict__ B) {
    __shared__ float As[16][132];
    __shared__ float Bs[16][132];
    int tid = threadIdx.x;
    int tx = tid & 15, ty = tid >> 4;
    int mBase = blockIdx.x * 128;
    int nBase = blockIdx.y * 128;
    float acc[8][8] = {};
    for (int k0 = 0; k0 < FF; k0 += 16) {
#pragma unroll
        for (int i = 0; i < 2; i++) {
            int li = tid + i * 256;
            int row = li >> 2;
            int c4 = li & 3;
            float4 va = *(const float4*)(A + (size_t)(mBase + row) * FF + k0 + c4 * 4);
            As[c4 * 4 + 0][row] = va.x;
            As[c4 * 4 + 1][row] = va.y;
            As[c4 * 4 + 2][row] = va.z;
            As[c4 * 4 + 3][row] = va.w;
            float4 vb = *(const float4*)(B + (size_t)(nBase + row) * FF + k0 + c4 * 4);
            Bs[c4 * 4 + 0][row] = vb.x;
            Bs[c4 * 4 + 1][row] = vb.y;
            Bs[c4 * 4 + 2][row] = vb.z;
            Bs[c4 * 4 + 3][row] = vb.w;
        }
        __syncthreads();
#pragma unroll
        for (int k = 0; k < 16; k++) {
            float a[8], b[8];
            *(float4*)(a)     = *(const float4*)&As[k][ty * 8];
            *(float4*)(a + 4) = *(const float4*)&As[k][ty * 8 + 4];
            *(float4*)(b)     = *(const float4*)&Bs[k][tx * 8];
            *(float4*)(b + 4) = *(const float4*)&Bs[k][tx * 8 + 4];
#pragma unroll
            for (int i2 = 0; i2 < 8; i2++)
#pragma unroll
                for (int j = 0; j < 8; j++)
                    acc[i2][j] += a[i2] * b[j];
        }
        __syncthreads();
    }
#pragma unroll
    for (int i2 = 0; i2 < 8; i2++) {
        float* op = g_xproj + (size_t)(mBase + ty * 8 + i2) * HH + nBase + tx * 8;
        *(float4*)(op)     = make_float4(acc[i2][0], acc[i2][1], acc[i2][2], acc[i2][3]);
        *(float4*)(op + 4) = make_float4(acc[i2][4], acc[i2][5], acc[i2][6], acc[i2][7]);
    }
}

// ============================================================
// K2: LIF-AdEx scan — one CTA per batch, 256 threads, h = {tid, tid+256}.
// Gather restructured into batches of 8: 16 independent LDG in flight,
// adds applied in ascending-j order (bit-identical trajectory).
// ============================================================
__global__ void __launch_bounds__(256, 1)
k_scan(float* __restrict__ d_out) {
    __shared__ unsigned zsm[2][16];
    __shared__ int offs[HH];

    int tid = threadIdx.x;            // = h_a; h_b = tid + 256
    int b = blockIdx.x;               // batch
    int lane = tid & 31, warp = tid >> 5;   // warp 0..7

    const char* base_a = (const char*)g_wrecT + (size_t)tid * 4;
    const char* base_b = base_a + 256 * 4;

    float va = 0.f, ia = 0.f, aa = 0.f;
    float vb = 0.f, ib = 0.f, ab = 0.f;
    bool za = false, zb = false;

    float xa_next = g_xproj[(size_t)b * HH + tid];
    float xb_next = g_xproj[(size_t)b * HH + tid + 256];

    for (int t = 0; t < TT; t++) {
        float ra = 0.f, rb = 0.f;
        if (t > 0) {
            int buf = (t - 1) & 1;
            // ---- build offset list (all warps duplicate; benign race, same values)
            unsigned mword = (lane < 16) ? zsm[buf][lane] : 0u;
            int cnt = __popc(mword);
            int pfx = cnt;
#pragma unroll
            for (int d = 1; d < 32; d <<= 1) {
                int y = __shfl_up_sync(0xffffffffu, pfx, d);
                if (lane >= d) pfx += y;
            }
            int n = __shfl_sync(0xffffffffu, pfx, 31);
            int base = pfx - cnt;
            while (mword) {
                int bit = __ffs(mword) - 1;
                mword &= mword - 1;
                offs[base++] = ((lane << 5) + bit) << 11;   // j * 512 floats * 4B
            }
            __syncwarp();

            // ---- dense gather, 8 rows per batch: 16 independent loads in flight
            int s = 0;
            for (; s + 8 <= n; s += 8) {
                int4 o0 = *(const int4*)&offs[s];
                int4 o1 = *(const int4*)&offs[s + 4];
                float a0 = *(const float*)(base_a + o0.x);
                float a1 = *(const float*)(base_a + o0.y);
                float a2 = *(const float*)(base_a + o0.z);
                float a3 = *(const float*)(base_a + o0.w);
                float a4 = *(const float*)(base_a + o1.x);
                float a5 = *(const float*)(base_a + o1.y);
                float a6 = *(const float*)(base_a + o1.z);
                float a7 = *(const float*)(base_a + o1.w);
                float b0 = *(const float*)(base_b + o0.x);
                float b1 = *(const float*)(base_b + o0.y);
                float b2 = *(const float*)(base_b + o0.z);
                float b3 = *(const float*)(base_b + o0.w);
                float b4 = *(const float*)(base_b + o1.x);
                float b5 = *(const float*)(base_b + o1.y);
                float b6 = *(const float*)(base_b + o1.z);
                float b7 = *(const float*)(base_b + o1.w);
                // ascending-j order preserved
                ra += a0; ra += a1; ra += a2; ra += a3;
                ra += a4; ra += a5; ra += a6; ra += a7;
                rb += b0; rb += b1; rb += b2; rb += b3;
                rb += b4; rb += b5; rb += b6; rb += b7;
            }
            for (; s < n; s++) {
                int o = offs[s];
                ra += *(const float*)(base_a + o);
                rb += *(const float*)(base_b + o);
            }
        }

        float xa = xa_next, xb = xb_next;
        if (t + 1 < TT) {
            xa_next = g_xproj[(size_t)((t + 1) * BB + b) * HH + tid];
            xb_next = g_xproj[(size_t)((t + 1) * BB + b) * HH + tid + 256];
        }

        // LIF-AdEx step for h_a
        {
            float ex = expf((va - 1.0f) * 2.0f);
            float dv = 0.1f * ((((0.0f - va) + 0.5f * ex) + ia) - aa);
            float v_dec = va + dv;
            float i_dec = ia - 0.2f * ia;
            float a_dec = aa + 0.002f * (4.0f * va - aa);
            za = (v_dec - 1.0f) > 0.0f;
            va = za ? 0.0f : v_dec;
            ia = (i_dec + xa) + ra;
            aa = a_dec + (za ? 0.02f : 0.0f);
        }
        // LIF-AdEx step for h_b
        {
            float ex = expf((vb - 1.0f) * 2.0f);
            float dv = 0.1f * ((((0.0f - vb) + 0.5f * ex) + ib) - ab);
            float v_dec = vb + dv;
            float i_dec = ib - 0.2f * ib;
            float a_dec = ab + 0.002f * (4.0f * vb - ab);
            zb = (v_dec - 1.0f) > 0.0f;
            vb = zb ? 0.0f : v_dec;
            ib = (i_dec + xb) + rb;
            ab = a_dec + (zb ? 0.02f : 0.0f);
        }

        unsigned ba = __ballot_sync(0xffffffffu, za);   // word 'warp'
        unsigned bb2 = __ballot_sync(0xffffffffu, zb);  // word 'warp+8'
        if (lane == 0) {
            zsm[t & 1][warp] = ba;
            zsm[t & 1][warp + 8] = bb2;
            unsigned* gs = g_spk + (size_t)(t * BB + b) * 16;
            gs[warp] = ba;
            gs[warp + 8] = bb2;
        }
        __syncthreads();
    }

    // final states (z, v, i, a) appended after out[T,B,O]
    size_t base = (size_t)TT * BB * OO;
    size_t oa = (size_t)b * HH + tid;
    size_t ob = oa + 256;
    d_out[base + oa] = za ? 1.0f : 0.0f;
    d_out[base + ob] = zb ? 1.0f : 0.0f;
    d_out[base + BB * HH + oa] = va;
    d_out[base + BB * HH + ob] = vb;
    d_out[base + 2 * BB * HH + oa] = ia;
    d_out[base + 2 * BB * HH + ob] = ib;
    d_out[base + 3 * BB * HH + oa] = aa;
    d_out[base + 3 * BB * HH + ob] = ab;
}

// ============================================================
// K3: lin[t,b,o] = b_out[o] + sum over spiking h of w_outT[h][o]
// ============================================================
__global__ void __launch_bounds__(128) k_lin(const float* __restrict__ b_out) {
    __shared__ unsigned zw[16];
    int tb = blockIdx.x;
    int tid = threadIdx.x;
    if (tid < 16) zw[tid] = g_spk[(size_t)tb * 16 + tid];
    __syncthreads();
    float acc = 0.f;
#pragma unroll
    for (int w16 = 0; w16 < 16; w16++) {
        unsigned m = zw[w16];
        const float* wp = g_woutT + (size_t)w16 * 32 * OO + tid;
        while (m) {
            int j = __ffs(m) - 1;
            m &= m - 1;
            acc += wp[j * OO];
        }
    }
    g_lin[(size_t)tb * OO + tid] = acc + b_out[tid];
}

// ============================================================
// K4a: filter phase A — local exp-filter scan per 50-step chunk (zero init)
// ============================================================
__global__ void __launch_bounds__(128) k_filter_a(float* __restrict__ out) {
    int b = blockIdx.x;
    int c = blockIdx.y;
    int o = threadIdx.x;
    const float C = (float)(0.001 * 223.1435511314);
    float y = 0.f;
    int t0 = c * CHLEN;
    for (int t = t0; t < t0 + CHLEN; t++) {
        float l = g_lin[((size_t)t * BB + b) * OO + o];
        y = y + C * (l - y);
        out[((size_t)t * BB + b) * OO + o] = y;
    }
    g_ytail[(b * NCHUNK + c) * OO + o] = y;
}

// ============================================================
// K4b: filter phase B — add carry correction d^(k+1) * carry_c
// ============================================================
__global__ void __launch_bounds__(128) k_filter_b(float* __restrict__ out) {
    int b = blockIdx.x;
    int c = blockIdx.y + 1;
    int o = threadIdx.x;
    const float C = (float)(0.001 * 223.1435511314);
    const float D = 1.0f - C;
    float d50 = 1.0f;
    for (int i = 0; i < CHLEN; i++) d50 *= D;
    float carry = 0.f;
    for (int j = 1; j <= c; j++)
        carry = g_ytail[(b * NCHUNK + (j - 1)) * OO + o] + d50 * carry;
    int t0 = c * CHLEN;
    float p = D;
    for (int t = t0; t < t0 + CHLEN; t++) {
        out[((size_t)t * BB + b) * OO + o] += p * carry;
        p *= D;
    }
}

// ============================================================
extern "C" void kernel_launch(void* const* d_in, const int* in_sizes, int n_in,
                              void* d_out, int out_size) {
    const float* x     = (const float*)d_in[0];  // [500,64,256]
    const float* w_in  = (const float*)d_in[1];  // [512,256]
    const float* w_rec = (const float*)d_in[2];  // [512,512]
    const float* w_out = (const float*)d_in[3];  // [128,512]
    const float* b_out = (const float*)d_in[4];  // [128]
    float* out = (float*)d_out;

    k_wtrans<<<(HH * OO + 255) / 256, 256>>>(w_out);
    k_wrect<<<dim3(16, 16), dim3(32, 8)>>>(w_rec);
    k_xproj<<<dim3((TT * BB) / 128, HH / 128), 256>>>(x, w_in);
    k_scan<<<BB, 256>>>(out);
    k_lin<<<TT * BB, 128>>>(b_out);
    k_filter_a<<<dim3(BB, NCHUNK), 128>>>(out);
    k_filter_b<<<dim3(BB, NCHUNK - 1), 128>>>(out);
}